// round 15
// baseline (speedup 1.0000x reference)
#include <cuda_runtime.h>
#include <cuda_fp16.h>
#include <stdint.h>

#define NN 100000
#define NE 1600000
#define D1 128
#define NBLK 391   // ceil(NN/256)

// ---------------- scratch (device globals) ------------------------------------
__device__ __half g_t16[NN * D1];   // layer-2 transformed features (fp16 storage)
__device__ float g_t3f[NN * 32];    // layer-3 transformed features (fp32)
__device__ float g_prev[NN * D1];   // layer output / residual carrier
__device__ float g_asrc[NN * 4];
__device__ float g_adst[NN * 4];
__device__ int   g_off[NN + 1];     // CSR offsets by dst
__device__ int   g_cur[NN];         // degree -> cursor
__device__ int   g_csrc[NE];        // src node per CSR slot
__device__ float g_vs[64];          // layer1: W1 @ attS per head [h][k16]
__device__ float g_vd[64];
__device__ __half g_w2t[128 * 128]; // W2 transposed to [n][k], half

__device__ __forceinline__ float lrelu(float x) { return x > 0.f ? x : 0.2f * x; }
__device__ __forceinline__ float pexp(float x) { return __expf(fminf(x, 80.f)); }
__device__ __forceinline__ float elu(float x) { return x > 0.f ? x : expm1f(x); }

__device__ __forceinline__ void mma_f16(float c[4], uint32_t a0, uint32_t a1,
                                        uint32_t a2, uint32_t a3,
                                        uint32_t b0, uint32_t b1) {
    asm volatile(
        "mma.sync.aligned.m16n8k16.row.col.f32.f16.f16.f32 "
        "{%0,%1,%2,%3}, {%4,%5,%6,%7}, {%8,%9}, {%0,%1,%2,%3};"
        : "+f"(c[0]), "+f"(c[1]), "+f"(c[2]), "+f"(c[3])
        : "r"(a0), "r"(a1), "r"(a2), "r"(a3), "r"(b0), "r"(b1));
}

// ================= front kernel: zero cursors + W2 transpose + prep1 ============
__global__ void k_front(const float* __restrict__ W2,
                        const float* __restrict__ W1,
                        const float* __restrict__ aS1,
                        const float* __restrict__ aD1) {
    int b = blockIdx.x;
    int t = threadIdx.x;
    if (b < NBLK) {
        int i = b * 256 + t;
        if (i < NN) g_cur[i] = 0;
    } else if (b < NBLK + 64) {
        int i = (b - NBLK) * 256 + t;      // 16384 elems
        int n = i >> 7, k = i & 127;
        g_w2t[n * 128 + k] = __float2half(W2[k * 128 + n]);
    } else {
        if (t < 64) {
            int h = t >> 4, k = t & 15;
            float vs = 0.f, vd = 0.f;
#pragma unroll
            for (int c = 0; c < 32; c++) {
                float wv = W1[k * 128 + h * 32 + c];
                vs = fmaf(wv, aS1[h * 32 + c], vs);
                vd = fmaf(wv, aD1[h * 32 + c], vd);
            }
            g_vs[t] = vs;
            g_vd[t] = vd;
        }
    }
}

// ================= hist + layer-1 logits (merged, disjoint block ranges) ========
__global__ void k_histlog(const int* __restrict__ dst, const float* __restrict__ x) {
    int b = blockIdx.x;
    int t = threadIdx.x;
    if (b < 1563) {
        int i = b * 256 + t;
        if (i >= NE / 4) return;
        int4 d = *(const int4*)&dst[i * 4];
        atomicAdd(&g_cur[d.x], 1);
        atomicAdd(&g_cur[d.y], 1);
        atomicAdd(&g_cur[d.z], 1);
        atomicAdd(&g_cur[d.w], 1);
    } else {
        int g = (b - 1563) * 256 + t;   // g = n*4 + h
        if (g >= NN * 4) return;
        int n = g >> 2, h = g & 3;
        const float* xr = &x[n * 16];
        float as = 0.f, ad = 0.f;
#pragma unroll
        for (int k = 0; k < 16; k++) {
            float xv = xr[k];
            as = fmaf(xv, g_vs[h * 16 + k], as);
            ad = fmaf(xv, g_vd[h * 16 + k], ad);
        }
        g_asrc[g] = as;
        g_adst[g] = ad;
    }
}

// ================= single-block exclusive scan (R2-proven pattern) ==============
__global__ void k_scan1() {   // <<<1, 1024>>>
    __shared__ int sm[1024];
    const int CH = (NN + 1023) / 1024;   // 98
    int t = threadIdx.x;
    int lo = t * CH, hi = min(lo + CH, NN);
    int sum = 0;
    for (int i = lo; i < hi; i++) sum += g_cur[i];
    sm[t] = sum;
    __syncthreads();
    for (int o = 1; o < 1024; o <<= 1) {
        int u = (t >= o) ? sm[t - o] : 0;
        __syncthreads();
        sm[t] += u;
        __syncthreads();
    }
    int run = (t == 0) ? 0 : sm[t - 1];
    for (int i = lo; i < hi; i++) {
        int d = g_cur[i];
        g_off[i] = run;
        g_cur[i] = run;
        run += d;
    }
    if (t == 1023) g_off[NN] = NE;
}

__global__ void k_reorder(const int* __restrict__ src, const int* __restrict__ dst) {
    int i = blockIdx.x * blockDim.x + threadIdx.x;   // 400000 threads
    if (i >= NE / 4) return;
    int4 d = *(const int4*)&dst[i * 4];
    int4 s = *(const int4*)&src[i * 4];
    int p0 = atomicAdd(&g_cur[d.x], 1);
    int p1 = atomicAdd(&g_cur[d.y], 1);
    int p2 = atomicAdd(&g_cur[d.z], 1);
    int p3 = atomicAdd(&g_cur[d.w], 1);
    g_csrc[p0] = s.x;
    g_csrc[p1] = s.y;
    g_csrc[p2] = s.z;
    g_csrc[p3] = s.w;
}

// ---- layer-1 gather in x-space (R12-exact) -------------------------------------
__global__ void k_gx(const float* __restrict__ x, const float* __restrict__ W,
                     const float* __restrict__ b) {
    __shared__ float Ws[16 * 128];
    __shared__ float agg[8][64];
    int t = threadIdx.x;
    {
        float4* wd = (float4*)Ws;
        const float4* wsrc = (const float4*)W;
        wd[t] = wsrc[t];
        wd[t + 256] = wsrc[t + 256];
    }
    __syncthreads();

    int n = (blockIdx.x * blockDim.x + t) >> 5;
    if (n >= NN) return;
    int lane = t & 31;
    int w = t >> 5;
    int k = lane & 15;
    int half = lane >> 4;
    int beg = g_off[n], end = g_off[n + 1];

    float4 ad = *(const float4*)&g_adst[n * 4];
    float4 acc = make_float4(0.f, 0.f, 0.f, 0.f);
    float4 s4 = make_float4(0.f, 0.f, 0.f, 0.f);

    for (int i = beg + half; i < end; i += 2) {
        int sv = g_csrc[i];
        float xv = __ldg(&x[sv * 16 + k]);
        float4 a = *(const float4*)&g_asrc[sv * 4];
        float4 p;
        p.x = pexp(lrelu(a.x + ad.x));
        p.y = pexp(lrelu(a.y + ad.y));
        p.z = pexp(lrelu(a.z + ad.z));
        p.w = pexp(lrelu(a.w + ad.w));
        s4.x += p.x; s4.y += p.y; s4.z += p.z; s4.w += p.w;
        acc.x = fmaf(p.x, xv, acc.x);
        acc.y = fmaf(p.y, xv, acc.y);
        acc.z = fmaf(p.z, xv, acc.z);
        acc.w = fmaf(p.w, xv, acc.w);
    }
    acc.x += __shfl_xor_sync(0xffffffffu, acc.x, 16);
    acc.y += __shfl_xor_sync(0xffffffffu, acc.y, 16);
    acc.z += __shfl_xor_sync(0xffffffffu, acc.z, 16);
    acc.w += __shfl_xor_sync(0xffffffffu, acc.w, 16);
    s4.x += __shfl_xor_sync(0xffffffffu, s4.x, 16);
    s4.y += __shfl_xor_sync(0xffffffffu, s4.y, 16);
    s4.z += __shfl_xor_sync(0xffffffffu, s4.z, 16);
    s4.w += __shfl_xor_sync(0xffffffffu, s4.w, 16);

    {
        float4 a = *(const float4*)&g_asrc[n * 4];
        float4 p;
        p.x = pexp(lrelu(a.x + ad.x));
        p.y = pexp(lrelu(a.y + ad.y));
        p.z = pexp(lrelu(a.z + ad.z));
        p.w = pexp(lrelu(a.w + ad.w));
        s4.x += p.x; s4.y += p.y; s4.z += p.z; s4.w += p.w;
        float xv = x[n * 16 + k];
        acc.x = fmaf(p.x, xv, acc.x);
        acc.y = fmaf(p.y, xv, acc.y);
        acc.z = fmaf(p.z, xv, acc.z);
        acc.w = fmaf(p.w, xv, acc.w);
    }

    if (half == 0) {
        agg[w][k]      = acc.x;
        agg[w][16 + k] = acc.y;
        agg[w][32 + k] = acc.z;
        agg[w][48 + k] = acc.w;
    }
    __syncwarp();

    int hd = lane >> 3;
    float sh = (hd == 0) ? s4.x : (hd == 1) ? s4.y : (hd == 2) ? s4.z : s4.w;
    float inv = 1.f / sh;
    float4 o = make_float4(0.f, 0.f, 0.f, 0.f);
#pragma unroll
    for (int kk = 0; kk < 16; kk++) {
        float av = agg[w][hd * 16 + kk];
        float4 wv = *(const float4*)&Ws[kk * 128 + lane * 4];
        o.x = fmaf(av, wv.x, o.x);
        o.y = fmaf(av, wv.y, o.y);
        o.z = fmaf(av, wv.z, o.z);
        o.w = fmaf(av, wv.w, o.w);
    }
    float4 bv = *(const float4*)&b[lane * 4];
    o.x = elu(o.x * inv + bv.x);
    o.y = elu(o.y * inv + bv.y);
    o.z = elu(o.z * inv + bv.z);
    o.w = elu(o.w * inv + bv.w);
    *(float4*)&g_prev[n * 128 + lane * 4] = o;
}

// ================= layer 2 GEMM via fp16 HMMA + fused attention logits ==========
__global__ void k_gemm2(const float* __restrict__ aS, const float* __restrict__ aD) {
    __shared__ __half xs[32 * 136];
    __shared__ __half ws[128 * 136];
    int t = threadIdx.x;
    int nb = blockIdx.x * 32;

    {
        const uint32_t* wsrc = (const uint32_t*)g_w2t;
        uint32_t* wd = (uint32_t*)ws;
        for (int i = t; i < 8192; i += 256) {
            int n = i >> 6, kk = i & 63;
            wd[n * 68 + kk] = wsrc[i];
        }
    }
    {
        uint32_t* xd = (uint32_t*)xs;
        for (int i = t; i < 2048; i += 256) {
            int r = i >> 6, kk = i & 63;
            int node = nb + r;
            float2 v = (node < NN) ? *(const float2*)&g_prev[node * 128 + kk * 2]
                                   : make_float2(0.f, 0.f);
            __half2 h = __floats2half2_rn(v.x, v.y);
            xd[r * 68 + kk] = *(uint32_t*)&h;
        }
    }
    __syncthreads();

    int lane = t & 31, wid = t >> 5;
    int g = lane >> 2, tig = lane & 3;
    int mt = wid >> 2;
    int nh = wid & 3;
    const uint32_t* xw = (const uint32_t*)xs;
    const uint32_t* ww = (const uint32_t*)ws;

    float c[4][4];
#pragma unroll
    for (int nt = 0; nt < 4; nt++)
#pragma unroll
        for (int j = 0; j < 4; j++) c[nt][j] = 0.f;

    int ra0 = (mt * 16 + g) * 68 + tig;
    int ra1 = ra0 + 8 * 68;
#pragma unroll
    for (int kt = 0; kt < 8; kt++) {
        int kw = kt * 8;
        uint32_t a0 = xw[ra0 + kw];
        uint32_t a1 = xw[ra1 + kw];
        uint32_t a2 = xw[ra0 + kw + 4];
        uint32_t a3 = xw[ra1 + kw + 4];
#pragma unroll
        for (int nt = 0; nt < 4; nt++) {
            int col = nh * 32 + nt * 8 + g;
            uint32_t b0 = ww[col * 68 + kw + tig];
            uint32_t b1 = ww[col * 68 + kw + tig + 4];
            mma_f16(c[nt], a0, a1, a2, a3, b0, b1);
        }
    }

    int node0 = nb + mt * 16 + g;
    int node1 = node0 + 8;
    float ps0 = 0.f, pd0 = 0.f, ps1 = 0.f, pd1 = 0.f;
#pragma unroll
    for (int nt = 0; nt < 4; nt++) {
        int col = nh * 32 + nt * 8 + 2 * tig;
        float as0 = aS[col], as1 = aS[col + 1];
        float ad0 = aD[col], ad1 = aD[col + 1];
        ps0 += c[nt][0] * as0 + c[nt][1] * as1;
        pd0 += c[nt][0] * ad0 + c[nt][1] * ad1;
        ps1 += c[nt][2] * as0 + c[nt][3] * as1;
        pd1 += c[nt][2] * ad0 + c[nt][3] * ad1;
        *(__half2*)&g_t16[node0 * 128 + col] = __floats2half2_rn(c[nt][0], c[nt][1]);
        *(__half2*)&g_t16[node1 * 128 + col] = __floats2half2_rn(c[nt][2], c[nt][3]);
    }
#pragma unroll
    for (int o = 1; o <= 2; o <<= 1) {
        ps0 += __shfl_xor_sync(0xffffffffu, ps0, o);
        pd0 += __shfl_xor_sync(0xffffffffu, pd0, o);
        ps1 += __shfl_xor_sync(0xffffffffu, ps1, o);
        pd1 += __shfl_xor_sync(0xffffffffu, pd1, o);
    }
    if (tig == 0) {
        g_asrc[node0 * 4 + nh] = ps0;
        g_adst[node0 * 4 + nh] = pd0;
        g_asrc[node1 * 4 + nh] = ps1;
        g_adst[node1 * 4 + nh] = pd1;
    }
}

// ================= layer 2 gather (R12-exact) ===================================
__device__ __forceinline__ void h4load(const __half* p, float& f0, float& f1, float& f2, float& f3) {
    uint2 u = *(const uint2*)p;
    float2 a = __half22float2(*(__half2*)&u.x);
    float2 b = __half22float2(*(__half2*)&u.y);
    f0 = a.x; f1 = a.y; f2 = b.x; f3 = b.y;
}

__global__ void k_gather4(const float* __restrict__ b) {
    int n = (blockIdx.x * blockDim.x + threadIdx.x) >> 5;
    if (n >= NN) return;
    int lane = threadIdx.x & 31;
    int hl = lane & 3;
    int hsrc = lane >> 3;
    int beg = g_off[n], end = g_off[n + 1];

    float4 ad = *(const float4*)&g_adst[n * 4];
    float adl = (hl == 0) ? ad.x : (hl == 1) ? ad.y : (hl == 2) ? ad.z : ad.w;

    float4 acc = make_float4(0.f, 0.f, 0.f, 0.f);
    float s = 0.f;
    int i = beg;
    for (; i + 4 <= end; i += 4) {
        int sv0 = g_csrc[i], sv1 = g_csrc[i + 1], sv2 = g_csrc[i + 2], sv3 = g_csrc[i + 3];
        float a0 = __ldg(&g_asrc[sv0 * 4 + hl]);
        float a1 = __ldg(&g_asrc[sv1 * 4 + hl]);
        float a2 = __ldg(&g_asrc[sv2 * 4 + hl]);
        float a3 = __ldg(&g_asrc[sv3 * 4 + hl]);
        float h0x, h0y, h0z, h0w, h1x, h1y, h1z, h1w;
        float h2x, h2y, h2z, h2w, h3x, h3y, h3z, h3w;
        h4load(&g_t16[sv0 * 128 + lane * 4], h0x, h0y, h0z, h0w);
        h4load(&g_t16[sv1 * 128 + lane * 4], h1x, h1y, h1z, h1w);
        h4load(&g_t16[sv2 * 128 + lane * 4], h2x, h2y, h2z, h2w);
        h4load(&g_t16[sv3 * 128 + lane * 4], h3x, h3y, h3z, h3w);
        float p0 = pexp(lrelu(a0 + adl));
        float p1 = pexp(lrelu(a1 + adl));
        float p2 = pexp(lrelu(a2 + adl));
        float p3 = pexp(lrelu(a3 + adl));
        s += (p0 + p1) + (p2 + p3);
        float q0 = __shfl_sync(0xffffffffu, p0, hsrc);
        float q1 = __shfl_sync(0xffffffffu, p1, hsrc);
        float q2 = __shfl_sync(0xffffffffu, p2, hsrc);
        float q3 = __shfl_sync(0xffffffffu, p3, hsrc);
        acc.x = fmaf(q0, h0x, acc.x); acc.y = fmaf(q0, h0y, acc.y);
        acc.z = fmaf(q0, h0z, acc.z); acc.w = fmaf(q0, h0w, acc.w);
        acc.x = fmaf(q1, h1x, acc.x); acc.y = fmaf(q1, h1y, acc.y);
        acc.z = fmaf(q1, h1z, acc.z); acc.w = fmaf(q1, h1w, acc.w);
        acc.x = fmaf(q2, h2x, acc.x); acc.y = fmaf(q2, h2y, acc.y);
        acc.z = fmaf(q2, h2z, acc.z); acc.w = fmaf(q2, h2w, acc.w);
        acc.x = fmaf(q3, h3x, acc.x); acc.y = fmaf(q3, h3y, acc.y);
        acc.z = fmaf(q3, h3z, acc.z); acc.w = fmaf(q3, h3w, acc.w);
    }
    for (; i < end; i++) {
        int sv = g_csrc[i];
        float a0 = __ldg(&g_asrc[sv * 4 + hl]);
        float h0x, h0y, h0z, h0w;
        h4load(&g_t16[sv * 128 + lane * 4], h0x, h0y, h0z, h0w);
        float p0 = pexp(lrelu(a0 + adl));
        s += p0;
        float q0 = __shfl_sync(0xffffffffu, p0, hsrc);
        acc.x = fmaf(q0, h0x, acc.x); acc.y = fmaf(q0, h0y, acc.y);
        acc.z = fmaf(q0, h0z, acc.z); acc.w = fmaf(q0, h0w, acc.w);
    }

    float4 asf = *(const float4*)&g_asrc[n * 4];
    float asl = (hl == 0) ? asf.x : (hl == 1) ? asf.y : (hl == 2) ? asf.z : asf.w;
    float pself = pexp(lrelu(asl + adl));
    s += pself;
    float sh = __shfl_sync(0xffffffffu, s, hsrc);
    float ph = __shfl_sync(0xffffffffu, pself, hsrc);

    float tsx, tsy, tsz, tsw;
    h4load(&g_t16[n * 128 + lane * 4], tsx, tsy, tsz, tsw);
    float4 bv = *(const float4*)&b[lane * 4];
    float inv = 1.f / sh;
    float4 pr = *(const float4*)&g_prev[n * 128 + lane * 4];
    float4 v;
    v.x = elu(fmaf(ph, tsx, acc.x) * inv + bv.x) + pr.x;
    v.y = elu(fmaf(ph, tsy, acc.y) * inv + bv.y) + pr.y;
    v.z = elu(fmaf(ph, tsz, acc.z) * inv + bv.z) + pr.z;
    v.w = elu(fmaf(ph, tsw, acc.w) * inv + bv.w) + pr.w;
    *(float4*)&g_prev[n * 128 + lane * 4] = v;
}

// ================= layer 3 GEMM (fp32, R12-exact) ===============================
__global__ void k_gemm3(const float* __restrict__ W,
                        const float* __restrict__ aS, const float* __restrict__ aD) {
    __shared__ float xs[32][128];
    __shared__ float ws[128][32];
    int t = threadIdx.x;
    int nb = blockIdx.x * 32;
    {
        const float4* srcp = (const float4*)&g_prev[nb * 128];
        float4* d = (float4*)xs;
#pragma unroll
        for (int r = 0; r < 8; r++) d[t + 128 * r] = srcp[t + 128 * r];
        const float4* wsrc = (const float4*)W;
        float4* wd = (float4*)ws;
#pragma unroll
        for (int r = 0; r < 8; r++) wd[t + 128 * r] = wsrc[t + 128 * r];
    }
    __syncthreads();

    int cg = t & 7;
    int ng = t >> 3;
    float4 a0 = make_float4(0,0,0,0), a1 = a0;
#pragma unroll 4
    for (int k = 0; k < 128; k++) {
        float4 wv = *(const float4*)&ws[k][cg * 4];
        float x0 = xs[ng * 2 + 0][k];
        float x1 = xs[ng * 2 + 1][k];
        a0.x = fmaf(x0, wv.x, a0.x); a0.y = fmaf(x0, wv.y, a0.y);
        a0.z = fmaf(x0, wv.z, a0.z); a0.w = fmaf(x0, wv.w, a0.w);
        a1.x = fmaf(x1, wv.x, a1.x); a1.y = fmaf(x1, wv.y, a1.y);
        a1.z = fmaf(x1, wv.z, a1.z); a1.w = fmaf(x1, wv.w, a1.w);
    }

    float4 aSv = *(const float4*)&aS[cg * 4];
    float4 aDv = *(const float4*)&aD[cg * 4];
    float4 accs[2] = {a0, a1};
#pragma unroll
    for (int j = 0; j < 2; j++) {
        int node = nb + ng * 2 + j;
        *(float4*)&g_t3f[node * 32 + cg * 4] = accs[j];
        float ps = accs[j].x * aSv.x + accs[j].y * aSv.y + accs[j].z * aSv.z + accs[j].w * aSv.w;
        float pd = accs[j].x * aDv.x + accs[j].y * aDv.y + accs[j].z * aDv.z + accs[j].w * aDv.w;
#pragma unroll
        for (int o = 4; o; o >>= 1) {
            ps += __shfl_xor_sync(0xffffffffu, ps, o);
            pd += __shfl_xor_sync(0xffffffffu, pd, o);
        }
        if (cg == 0) {
            g_asrc[node] = ps;
            g_adst[node] = pd;
        }
    }
}

// ================= layer 3 gather + output heads (fp32, R12-exact) ==============
__global__ void k_gather1(const float* __restrict__ b3,
                          const float* __restrict__ rw, const float* __restrict__ rb,
                          const float* __restrict__ cw, const float* __restrict__ cb,
                          float* __restrict__ out) {
    int n = (blockIdx.x * blockDim.x + threadIdx.x) >> 5;
    if (n >= NN) return;
    int lane = threadIdx.x & 31;
    int beg = g_off[n], end = g_off[n + 1];

    float adn = g_adst[n];
    float acc = 0.f, s = 0.f;
    int i = beg;
    for (; i + 4 <= end; i += 4) {
        int sv0 = g_csrc[i], sv1 = g_csrc[i + 1], sv2 = g_csrc[i + 2], sv3 = g_csrc[i + 3];
        float a0 = __ldg(&g_asrc[sv0]);
        float a1 = __ldg(&g_asrc[sv1]);
        float a2 = __ldg(&g_asrc[sv2]);
        float a3 = __ldg(&g_asrc[sv3]);
        float h0 = g_t3f[sv0 * 32 + lane];
        float h1 = g_t3f[sv1 * 32 + lane];
        float h2 = g_t3f[sv2 * 32 + lane];
        float h3 = g_t3f[sv3 * 32 + lane];
        float p0 = pexp(lrelu(a0 + adn));
        float p1 = pexp(lrelu(a1 + adn));
        float p2 = pexp(lrelu(a2 + adn));
        float p3 = pexp(lrelu(a3 + adn));
        s += (p0 + p1) + (p2 + p3);
        acc = fmaf(p0, h0, acc);
        acc = fmaf(p1, h1, acc);
        acc = fmaf(p2, h2, acc);
        acc = fmaf(p3, h3, acc);
    }
    for (; i < end; i++) {
        int sv = g_csrc[i];
        float p = pexp(lrelu(__ldg(&g_asrc[sv]) + adn));
        s += p;
        acc = fmaf(p, g_t3f[sv * 32 + lane], acc);
    }

    float ps = pexp(lrelu(g_asrc[n] + adn));
    s += ps;
    float val = elu(fmaf(ps, g_t3f[n * 32 + lane], acc) / s + b3[lane]);

    float r = val * rw[lane], cl = val * cw[lane];
#pragma unroll
    for (int o = 16; o; o >>= 1) {
        r += __shfl_xor_sync(0xffffffffu, r, o);
        cl += __shfl_xor_sync(0xffffffffu, cl, o);
    }
    if (lane == 0) {
        out[n] = r + rb[0];
        out[NN + n] = cl + cb[0];
    }
}

// ================= launch (pure kernel launches; capture-safe) ==================
extern "C" void kernel_launch(void* const* d_in, const int* in_sizes, int n_in,
                              void* d_out, int out_size) {
    const float* x    = (const float*)d_in[0];
    const int*   ei   = (const int*)d_in[1];
    const float* W1   = (const float*)d_in[2];
    const float* aS1  = (const float*)d_in[3];
    const float* aD1  = (const float*)d_in[4];
    const float* b1   = (const float*)d_in[5];
    const float* W2   = (const float*)d_in[6];
    const float* aS2  = (const float*)d_in[7];
    const float* aD2  = (const float*)d_in[8];
    const float* b2   = (const float*)d_in[9];
    const float* W3   = (const float*)d_in[10];
    const float* aS3  = (const float*)d_in[11];
    const float* aD3  = (const float*)d_in[12];
    const float* b3   = (const float*)d_in[13];
    const float* regw = (const float*)d_in[14];
    const float* regb = (const float*)d_in[15];
    const float* clsw = (const float*)d_in[16];
    const float* clsb = (const float*)d_in[17];
    float* out = (float*)d_out;

    const int* src = ei;
    const int* dst = ei + NE;

    // 1. front: zero cursors + W2 transpose + prep1
    k_front<<<NBLK + 65, 256>>>(W2, W1, aS1, aD1);
    // 2. histogram + layer-1 logits (merged, disjoint block ranges)
    k_histlog<<<3126, 256>>>(dst, x);
    // 3. single-block scan -> g_off, g_cur
    k_scan1<<<1, 1024>>>();
    // 4. reorder
    k_reorder<<<(NE / 4 + 255) / 256, 256>>>(src, dst);
    // 5. layer 1 gather (x-space)
    k_gx<<<12500, 256>>>(x, W1, b1);
    // 6-7. layer 2: HMMA GEMM with fused logits, gather (+residual)
    k_gemm2<<<3125, 256>>>(aS2, aD2);
    k_gather4<<<12500, 256>>>(b2);
    // 8-9. layer 3 + output heads
    k_gemm3<<<3125, 128>>>(W3, aS3, aD3);
    k_gather1<<<12500, 256>>>(b3, regw, regb, clsw, clsb, out);
}

// round 16
// speedup vs baseline: 1.3800x; 1.3800x over previous
#include <cuda_runtime.h>
#include <cuda_fp16.h>
#include <stdint.h>

#define NN 100000
#define NE 1600000
#define D1 128
#define NBLK 391   // ceil(NN/256)

// ---------------- scratch (device globals) ------------------------------------
__device__ __half g_t16[NN * D1];   // layer-2 transformed features (fp16 storage)
__device__ float g_t3f[NN * 32];    // layer-3 transformed features (fp32)
__device__ float g_prev[NN * D1];   // layer output / residual carrier
__device__ float g_asrc[NN * 4];
__device__ float g_adst[NN * 4];
__device__ int   g_off[NN + 1];     // CSR offsets by dst
__device__ int   g_cur[NN];         // degree -> cursor
__device__ int   g_csrc[NE];        // src node per CSR slot
__device__ int   g_bsum[512];
__device__ int   g_boff[512];
__device__ float g_vs[64];          // layer1: W1 @ attS per head [h][k16]
__device__ float g_vd[64];
__device__ __half g_w2t[128 * 128]; // W2 transposed to [n][k], half

__device__ __forceinline__ float lrelu(float x) { return x > 0.f ? x : 0.2f * x; }
__device__ __forceinline__ float pexp(float x) { return __expf(fminf(x, 80.f)); }
__device__ __forceinline__ float elu(float x) { return x > 0.f ? x : expm1f(x); }

__device__ __forceinline__ void mma_f16(float c[4], uint32_t a0, uint32_t a1,
                                        uint32_t a2, uint32_t a3,
                                        uint32_t b0, uint32_t b1) {
    asm volatile(
        "mma.sync.aligned.m16n8k16.row.col.f32.f16.f16.f32 "
        "{%0,%1,%2,%3}, {%4,%5,%6,%7}, {%8,%9}, {%0,%1,%2,%3};"
        : "+f"(c[0]), "+f"(c[1]), "+f"(c[2]), "+f"(c[3])
        : "r"(a0), "r"(a1), "r"(a2), "r"(a3), "r"(b0), "r"(b1));
}

// ================= front kernel: zero cursors + W2 transpose + prep1 ============
// blocks [0,391): zero g_cur | [391,455): w2t | block 455: prep1
__global__ void k_front(const float* __restrict__ W2,
                        const float* __restrict__ W1,
                        const float* __restrict__ aS1,
                        const float* __restrict__ aD1) {
    int b = blockIdx.x;
    int t = threadIdx.x;
    if (b < NBLK) {
        int i = b * 256 + t;
        if (i < NN) g_cur[i] = 0;
    } else if (b < NBLK + 64) {
        int i = (b - NBLK) * 256 + t;      // 16384 elems
        int n = i >> 7, k = i & 127;
        g_w2t[n * 128 + k] = __float2half(W2[k * 128 + n]);
    } else {
        if (t < 64) {
            int h = t >> 4, k = t & 15;
            float vs = 0.f, vd = 0.f;
#pragma unroll
            for (int c = 0; c < 32; c++) {
                float wv = W1[k * 128 + h * 32 + c];
                vs = fmaf(wv, aS1[h * 32 + c], vs);
                vd = fmaf(wv, aD1[h * 32 + c], vd);
            }
            g_vs[t] = vs;
            g_vd[t] = vd;
        }
    }
}

// ================= hist + layer-1 logits (merged, disjoint block ranges) ========
// blocks [0,1563): histogram (4 edges/thread, int4) | [1563,3126): logits1
__global__ void k_histlog(const int* __restrict__ dst, const float* __restrict__ x) {
    int b = blockIdx.x;
    int t = threadIdx.x;
    if (b < 1563) {
        int i = b * 256 + t;
        if (i >= NE / 4) return;
        int4 d = *(const int4*)&dst[i * 4];
        atomicAdd(&g_cur[d.x], 1);
        atomicAdd(&g_cur[d.y], 1);
        atomicAdd(&g_cur[d.z], 1);
        atomicAdd(&g_cur[d.w], 1);
    } else {
        int g = (b - 1563) * 256 + t;   // g = n*4 + h
        if (g >= NN * 4) return;
        int n = g >> 2, h = g & 3;
        const float* xr = &x[n * 16];
        float as = 0.f, ad = 0.f;
#pragma unroll
        for (int k = 0; k < 16; k++) {
            float xv = xr[k];
            as = fmaf(xv, g_vs[h * 16 + k], as);
            ad = fmaf(xv, g_vd[h * 16 + k], ad);
        }
        g_asrc[g] = as;
        g_adst[g] = ad;
    }
}

// ================= CSR scan (3-kernel hierarchical, measured-best) ==============
__global__ void k_bsum() {
    __shared__ int sm[256];
    int b = blockIdx.x, t = threadIdx.x;
    int i = b * 256 + t;
    sm[t] = (i < NN) ? g_cur[i] : 0;
    __syncthreads();
    for (int o = 128; o; o >>= 1) {
        if (t < o) sm[t] += sm[t + o];
        __syncthreads();
    }
    if (t == 0) g_bsum[b] = sm[0];
}

__global__ void k_bscan() {
    __shared__ int sm[512];
    int t = threadIdx.x;
    int v = (t < NBLK) ? g_bsum[t] : 0;
    sm[t] = v;
    __syncthreads();
    for (int o = 1; o < 512; o <<= 1) {
        int u = (t >= o) ? sm[t - o] : 0;
        __syncthreads();
        sm[t] += u;
        __syncthreads();
    }
    if (t < NBLK) g_boff[t] = sm[t] - v;
    if (t == 0) g_off[NN] = NE;
}

__global__ void k_local() {
    __shared__ int sm[256];
    int b = blockIdx.x, t = threadIdx.x;
    int i = b * 256 + t;
    int v = (i < NN) ? g_cur[i] : 0;
    sm[t] = v;
    __syncthreads();
    for (int o = 1; o < 256; o <<= 1) {
        int u = (t >= o) ? sm[t - o] : 0;
        __syncthreads();
        sm[t] += u;
        __syncthreads();
    }
    if (i < NN) {
        int off = g_boff[b] + sm[t] - v;
        g_off[i] = off;
        g_cur[i] = off;
    }
}

__global__ void k_reorder(const int* __restrict__ src, const int* __restrict__ dst) {
    int i = blockIdx.x * blockDim.x + threadIdx.x;   // 400000 threads
    if (i >= NE / 4) return;
    int4 d = *(const int4*)&dst[i * 4];
    int4 s = *(const int4*)&src[i * 4];
    int p0 = atomicAdd(&g_cur[d.x], 1);
    int p1 = atomicAdd(&g_cur[d.y], 1);
    int p2 = atomicAdd(&g_cur[d.z], 1);
    int p3 = atomicAdd(&g_cur[d.w], 1);
    g_csrc[p0] = s.x;
    g_csrc[p1] = s.y;
    g_csrc[p2] = s.z;
    g_csrc[p3] = s.w;
}

// ---- layer-1 gather in x-space -------------------------------------------------
__global__ void k_gx(const float* __restrict__ x, const float* __restrict__ W,
                     const float* __restrict__ b) {
    __shared__ float Ws[16 * 128];
    __shared__ float agg[8][64];
    int t = threadIdx.x;
    {
        float4* wd = (float4*)Ws;
        const float4* wsrc = (const float4*)W;
        wd[t] = wsrc[t];
        wd[t + 256] = wsrc[t + 256];
    }
    __syncthreads();

    int n = (blockIdx.x * blockDim.x + t) >> 5;
    if (n >= NN) return;
    int lane = t & 31;
    int w = t >> 5;
    int k = lane & 15;
    int half = lane >> 4;
    int beg = g_off[n], end = g_off[n + 1];

    float4 ad = *(const float4*)&g_adst[n * 4];
    float4 acc = make_float4(0.f, 0.f, 0.f, 0.f);
    float4 s4 = make_float4(0.f, 0.f, 0.f, 0.f);

    for (int i = beg + half; i < end; i += 2) {
        int sv = g_csrc[i];
        float xv = __ldg(&x[sv * 16 + k]);
        float4 a = *(const float4*)&g_asrc[sv * 4];
        float4 p;
        p.x = pexp(lrelu(a.x + ad.x));
        p.y = pexp(lrelu(a.y + ad.y));
        p.z = pexp(lrelu(a.z + ad.z));
        p.w = pexp(lrelu(a.w + ad.w));
        s4.x += p.x; s4.y += p.y; s4.z += p.z; s4.w += p.w;
        acc.x = fmaf(p.x, xv, acc.x);
        acc.y = fmaf(p.y, xv, acc.y);
        acc.z = fmaf(p.z, xv, acc.z);
        acc.w = fmaf(p.w, xv, acc.w);
    }
    acc.x += __shfl_xor_sync(0xffffffffu, acc.x, 16);
    acc.y += __shfl_xor_sync(0xffffffffu, acc.y, 16);
    acc.z += __shfl_xor_sync(0xffffffffu, acc.z, 16);
    acc.w += __shfl_xor_sync(0xffffffffu, acc.w, 16);
    s4.x += __shfl_xor_sync(0xffffffffu, s4.x, 16);
    s4.y += __shfl_xor_sync(0xffffffffu, s4.y, 16);
    s4.z += __shfl_xor_sync(0xffffffffu, s4.z, 16);
    s4.w += __shfl_xor_sync(0xffffffffu, s4.w, 16);

    {
        float4 a = *(const float4*)&g_asrc[n * 4];
        float4 p;
        p.x = pexp(lrelu(a.x + ad.x));
        p.y = pexp(lrelu(a.y + ad.y));
        p.z = pexp(lrelu(a.z + ad.z));
        p.w = pexp(lrelu(a.w + ad.w));
        s4.x += p.x; s4.y += p.y; s4.z += p.z; s4.w += p.w;
        float xv = x[n * 16 + k];
        acc.x = fmaf(p.x, xv, acc.x);
        acc.y = fmaf(p.y, xv, acc.y);
        acc.z = fmaf(p.z, xv, acc.z);
        acc.w = fmaf(p.w, xv, acc.w);
    }

    if (half == 0) {
        agg[w][k]      = acc.x;
        agg[w][16 + k] = acc.y;
        agg[w][32 + k] = acc.z;
        agg[w][48 + k] = acc.w;
    }
    __syncwarp();

    int hd = lane >> 3;
    float sh = (hd == 0) ? s4.x : (hd == 1) ? s4.y : (hd == 2) ? s4.z : s4.w;
    float inv = 1.f / sh;
    float4 o = make_float4(0.f, 0.f, 0.f, 0.f);
#pragma unroll
    for (int kk = 0; kk < 16; kk++) {
        float av = agg[w][hd * 16 + kk];
        float4 wv = *(const float4*)&Ws[kk * 128 + lane * 4];
        o.x = fmaf(av, wv.x, o.x);
        o.y = fmaf(av, wv.y, o.y);
        o.z = fmaf(av, wv.z, o.z);
        o.w = fmaf(av, wv.w, o.w);
    }
    float4 bv = *(const float4*)&b[lane * 4];
    o.x = elu(o.x * inv + bv.x);
    o.y = elu(o.y * inv + bv.y);
    o.z = elu(o.z * inv + bv.z);
    o.w = elu(o.w * inv + bv.w);
    *(float4*)&g_prev[n * 128 + lane * 4] = o;
}

// ================= layer 2 GEMM via fp16 HMMA + fused attention logits ==========
__global__ void k_gemm2(const float* __restrict__ aS, const float* __restrict__ aD) {
    __shared__ __half xs[32 * 136];
    __shared__ __half ws[128 * 136];
    int t = threadIdx.x;
    int nb = blockIdx.x * 32;

    {
        const uint32_t* wsrc = (const uint32_t*)g_w2t;
        uint32_t* wd = (uint32_t*)ws;
        for (int i = t; i < 8192; i += 256) {
            int n = i >> 6, kk = i & 63;
            wd[n * 68 + kk] = wsrc[i];
        }
    }
    {
        uint32_t* xd = (uint32_t*)xs;
        for (int i = t; i < 2048; i += 256) {
            int r = i >> 6, kk = i & 63;
            int node = nb + r;
            float2 v = (node < NN) ? *(const float2*)&g_prev[node * 128 + kk * 2]
                                   : make_float2(0.f, 0.f);
            __half2 h = __floats2half2_rn(v.x, v.y);
            xd[r * 68 + kk] = *(uint32_t*)&h;
        }
    }
    __syncthreads();

    int lane = t & 31, wid = t >> 5;
    int g = lane >> 2, tig = lane & 3;
    int mt = wid >> 2;
    int nh = wid & 3;
    const uint32_t* xw = (const uint32_t*)xs;
    const uint32_t* ww = (const uint32_t*)ws;

    float c[4][4];
#pragma unroll
    for (int nt = 0; nt < 4; nt++)
#pragma unroll
        for (int j = 0; j < 4; j++) c[nt][j] = 0.f;

    int ra0 = (mt * 16 + g) * 68 + tig;
    int ra1 = ra0 + 8 * 68;
#pragma unroll
    for (int kt = 0; kt < 8; kt++) {
        int kw = kt * 8;
        uint32_t a0 = xw[ra0 + kw];
        uint32_t a1 = xw[ra1 + kw];
        uint32_t a2 = xw[ra0 + kw + 4];
        uint32_t a3 = xw[ra1 + kw + 4];
#pragma unroll
        for (int nt = 0; nt < 4; nt++) {
            int col = nh * 32 + nt * 8 + g;
            uint32_t b0 = ww[col * 68 + kw + tig];
            uint32_t b1 = ww[col * 68 + kw + tig + 4];
            mma_f16(c[nt], a0, a1, a2, a3, b0, b1);
        }
    }

    int node0 = nb + mt * 16 + g;
    int node1 = node0 + 8;
    float ps0 = 0.f, pd0 = 0.f, ps1 = 0.f, pd1 = 0.f;
#pragma unroll
    for (int nt = 0; nt < 4; nt++) {
        int col = nh * 32 + nt * 8 + 2 * tig;
        float as0 = aS[col], as1 = aS[col + 1];
        float ad0 = aD[col], ad1 = aD[col + 1];
        ps0 += c[nt][0] * as0 + c[nt][1] * as1;
        pd0 += c[nt][0] * ad0 + c[nt][1] * ad1;
        ps1 += c[nt][2] * as0 + c[nt][3] * as1;
        pd1 += c[nt][2] * ad0 + c[nt][3] * ad1;
        *(__half2*)&g_t16[node0 * 128 + col] = __floats2half2_rn(c[nt][0], c[nt][1]);
        *(__half2*)&g_t16[node1 * 128 + col] = __floats2half2_rn(c[nt][2], c[nt][3]);
    }
#pragma unroll
    for (int o = 1; o <= 2; o <<= 1) {
        ps0 += __shfl_xor_sync(0xffffffffu, ps0, o);
        pd0 += __shfl_xor_sync(0xffffffffu, pd0, o);
        ps1 += __shfl_xor_sync(0xffffffffu, ps1, o);
        pd1 += __shfl_xor_sync(0xffffffffu, pd1, o);
    }
    if (tig == 0) {
        g_asrc[node0 * 4 + nh] = ps0;
        g_adst[node0 * 4 + nh] = pd0;
        g_asrc[node1 * 4 + nh] = ps1;
        g_adst[node1 * 4 + nh] = pd1;
    }
}

// ================= layer 2 gather (fp16 rows, unroll 4) =========================
__device__ __forceinline__ void h4load(const __half* p, float& f0, float& f1, float& f2, float& f3) {
    uint2 u = *(const uint2*)p;
    float2 a = __half22float2(*(__half2*)&u.x);
    float2 b = __half22float2(*(__half2*)&u.y);
    f0 = a.x; f1 = a.y; f2 = b.x; f3 = b.y;
}

__global__ void k_gather4(const float* __restrict__ b) {
    int n = (blockIdx.x * blockDim.x + threadIdx.x) >> 5;
    if (n >= NN) return;
    int lane = threadIdx.x & 31;
    int hl = lane & 3;
    int hsrc = lane >> 3;
    int beg = g_off[n], end = g_off[n + 1];

    float4 ad = *(const float4*)&g_adst[n * 4];
    float adl = (hl == 0) ? ad.x : (hl == 1) ? ad.y : (hl == 2) ? ad.z : ad.w;

    float4 acc = make_float4(0.f, 0.f, 0.f, 0.f);
    float s = 0.f;
    int i = beg;
    for (; i + 4 <= end; i += 4) {
        int sv0 = g_csrc[i], sv1 = g_csrc[i + 1], sv2 = g_csrc[i + 2], sv3 = g_csrc[i + 3];
        float a0 = __ldg(&g_asrc[sv0 * 4 + hl]);
        float a1 = __ldg(&g_asrc[sv1 * 4 + hl]);
        float a2 = __ldg(&g_asrc[sv2 * 4 + hl]);
        float a3 = __ldg(&g_asrc[sv3 * 4 + hl]);
        float h0x, h0y, h0z, h0w, h1x, h1y, h1z, h1w;
        float h2x, h2y, h2z, h2w, h3x, h3y, h3z, h3w;
        h4load(&g_t16[sv0 * 128 + lane * 4], h0x, h0y, h0z, h0w);
        h4load(&g_t16[sv1 * 128 + lane * 4], h1x, h1y, h1z, h1w);
        h4load(&g_t16[sv2 * 128 + lane * 4], h2x, h2y, h2z, h2w);
        h4load(&g_t16[sv3 * 128 + lane * 4], h3x, h3y, h3z, h3w);
        float p0 = pexp(lrelu(a0 + adl));
        float p1 = pexp(lrelu(a1 + adl));
        float p2 = pexp(lrelu(a2 + adl));
        float p3 = pexp(lrelu(a3 + adl));
        s += (p0 + p1) + (p2 + p3);
        float q0 = __shfl_sync(0xffffffffu, p0, hsrc);
        float q1 = __shfl_sync(0xffffffffu, p1, hsrc);
        float q2 = __shfl_sync(0xffffffffu, p2, hsrc);
        float q3 = __shfl_sync(0xffffffffu, p3, hsrc);
        acc.x = fmaf(q0, h0x, acc.x); acc.y = fmaf(q0, h0y, acc.y);
        acc.z = fmaf(q0, h0z, acc.z); acc.w = fmaf(q0, h0w, acc.w);
        acc.x = fmaf(q1, h1x, acc.x); acc.y = fmaf(q1, h1y, acc.y);
        acc.z = fmaf(q1, h1z, acc.z); acc.w = fmaf(q1, h1w, acc.w);
        acc.x = fmaf(q2, h2x, acc.x); acc.y = fmaf(q2, h2y, acc.y);
        acc.z = fmaf(q2, h2z, acc.z); acc.w = fmaf(q2, h2w, acc.w);
        acc.x = fmaf(q3, h3x, acc.x); acc.y = fmaf(q3, h3y, acc.y);
        acc.z = fmaf(q3, h3z, acc.z); acc.w = fmaf(q3, h3w, acc.w);
    }
    for (; i < end; i++) {
        int sv = g_csrc[i];
        float a0 = __ldg(&g_asrc[sv * 4 + hl]);
        float h0x, h0y, h0z, h0w;
        h4load(&g_t16[sv * 128 + lane * 4], h0x, h0y, h0z, h0w);
        float p0 = pexp(lrelu(a0 + adl));
        s += p0;
        float q0 = __shfl_sync(0xffffffffu, p0, hsrc);
        acc.x = fmaf(q0, h0x, acc.x); acc.y = fmaf(q0, h0y, acc.y);
        acc.z = fmaf(q0, h0z, acc.z); acc.w = fmaf(q0, h0w, acc.w);
    }

    float4 asf = *(const float4*)&g_asrc[n * 4];
    float asl = (hl == 0) ? asf.x : (hl == 1) ? asf.y : (hl == 2) ? asf.z : asf.w;
    float pself = pexp(lrelu(asl + adl));
    s += pself;
    float sh = __shfl_sync(0xffffffffu, s, hsrc);
    float ph = __shfl_sync(0xffffffffu, pself, hsrc);

    float tsx, tsy, tsz, tsw;
    h4load(&g_t16[n * 128 + lane * 4], tsx, tsy, tsz, tsw);
    float4 bv = *(const float4*)&b[lane * 4];
    float inv = 1.f / sh;
    float4 pr = *(const float4*)&g_prev[n * 128 + lane * 4];
    float4 v;
    v.x = elu(fmaf(ph, tsx, acc.x) * inv + bv.x) + pr.x;
    v.y = elu(fmaf(ph, tsy, acc.y) * inv + bv.y) + pr.y;
    v.z = elu(fmaf(ph, tsz, acc.z) * inv + bv.z) + pr.z;
    v.w = elu(fmaf(ph, tsw, acc.w) * inv + bv.w) + pr.w;
    *(float4*)&g_prev[n * 128 + lane * 4] = v;
}

// ================= layer 3 GEMM (fp32) ==========================================
__global__ void k_gemm3(const float* __restrict__ W,
                        const float* __restrict__ aS, const float* __restrict__ aD) {
    __shared__ float xs[32][128];
    __shared__ float ws[128][32];
    int t = threadIdx.x;
    int nb = blockIdx.x * 32;
    {
        const float4* srcp = (const float4*)&g_prev[nb * 128];
        float4* d = (float4*)xs;
#pragma unroll
        for (int r = 0; r < 8; r++) d[t + 128 * r] = srcp[t + 128 * r];
        const float4* wsrc = (const float4*)W;
        float4* wd = (float4*)ws;
#pragma unroll
        for (int r = 0; r < 8; r++) wd[t + 128 * r] = wsrc[t + 128 * r];
    }
    __syncthreads();

    int cg = t & 7;
    int ng = t >> 3;
    float4 a0 = make_float4(0,0,0,0), a1 = a0;
#pragma unroll 4
    for (int k = 0; k < 128; k++) {
        float4 wv = *(const float4*)&ws[k][cg * 4];
        float x0 = xs[ng * 2 + 0][k];
        float x1 = xs[ng * 2 + 1][k];
        a0.x = fmaf(x0, wv.x, a0.x); a0.y = fmaf(x0, wv.y, a0.y);
        a0.z = fmaf(x0, wv.z, a0.z); a0.w = fmaf(x0, wv.w, a0.w);
        a1.x = fmaf(x1, wv.x, a1.x); a1.y = fmaf(x1, wv.y, a1.y);
        a1.z = fmaf(x1, wv.z, a1.z); a1.w = fmaf(x1, wv.w, a1.w);
    }

    float4 aSv = *(const float4*)&aS[cg * 4];
    float4 aDv = *(const float4*)&aD[cg * 4];
    float4 accs[2] = {a0, a1};
#pragma unroll
    for (int j = 0; j < 2; j++) {
        int node = nb + ng * 2 + j;
        *(float4*)&g_t3f[node * 32 + cg * 4] = accs[j];
        float ps = accs[j].x * aSv.x + accs[j].y * aSv.y + accs[j].z * aSv.z + accs[j].w * aSv.w;
        float pd = accs[j].x * aDv.x + accs[j].y * aDv.y + accs[j].z * aDv.z + accs[j].w * aDv.w;
#pragma unroll
        for (int o = 4; o; o >>= 1) {
            ps += __shfl_xor_sync(0xffffffffu, ps, o);
            pd += __shfl_xor_sync(0xffffffffu, pd, o);
        }
        if (cg == 0) {
            g_asrc[node] = ps;
            g_adst[node] = pd;
        }
    }
}

// ================= layer 3 gather + output heads (fp32) =========================
__global__ void k_gather1(const float* __restrict__ b3,
                          const float* __restrict__ rw, const float* __restrict__ rb,
                          const float* __restrict__ cw, const float* __restrict__ cb,
                          float* __restrict__ out) {
    int n = (blockIdx.x * blockDim.x + threadIdx.x) >> 5;
    if (n >= NN) return;
    int lane = threadIdx.x & 31;
    int beg = g_off[n], end = g_off[n + 1];

    float adn = g_adst[n];
    float acc = 0.f, s = 0.f;
    int i = beg;
    for (; i + 4 <= end; i += 4) {
        int sv0 = g_csrc[i], sv1 = g_csrc[i + 1], sv2 = g_csrc[i + 2], sv3 = g_csrc[i + 3];
        float a0 = __ldg(&g_asrc[sv0]);
        float a1 = __ldg(&g_asrc[sv1]);
        float a2 = __ldg(&g_asrc[sv2]);
        float a3 = __ldg(&g_asrc[sv3]);
        float h0 = g_t3f[sv0 * 32 + lane];
        float h1 = g_t3f[sv1 * 32 + lane];
        float h2 = g_t3f[sv2 * 32 + lane];
        float h3 = g_t3f[sv3 * 32 + lane];
        float p0 = pexp(lrelu(a0 + adn));
        float p1 = pexp(lrelu(a1 + adn));
        float p2 = pexp(lrelu(a2 + adn));
        float p3 = pexp(lrelu(a3 + adn));
        s += (p0 + p1) + (p2 + p3);
        acc = fmaf(p0, h0, acc);
        acc = fmaf(p1, h1, acc);
        acc = fmaf(p2, h2, acc);
        acc = fmaf(p3, h3, acc);
    }
    for (; i < end; i++) {
        int sv = g_csrc[i];
        float p = pexp(lrelu(__ldg(&g_asrc[sv]) + adn));
        s += p;
        acc = fmaf(p, g_t3f[sv * 32 + lane], acc);
    }

    float ps = pexp(lrelu(g_asrc[n] + adn));
    s += ps;
    float val = elu(fmaf(ps, g_t3f[n * 32 + lane], acc) / s + b3[lane]);

    float r = val * rw[lane], cl = val * cw[lane];
#pragma unroll
    for (int o = 16; o; o >>= 1) {
        r += __shfl_xor_sync(0xffffffffu, r, o);
        cl += __shfl_xor_sync(0xffffffffu, cl, o);
    }
    if (lane == 0) {
        out[n] = r + rb[0];
        out[NN + n] = cl + cb[0];
    }
}

// ================= launch (pure kernel launches; capture-safe) ==================
extern "C" void kernel_launch(void* const* d_in, const int* in_sizes, int n_in,
                              void* d_out, int out_size) {
    const float* x    = (const float*)d_in[0];
    const int*   ei   = (const int*)d_in[1];
    const float* W1   = (const float*)d_in[2];
    const float* aS1  = (const float*)d_in[3];
    const float* aD1  = (const float*)d_in[4];
    const float* b1   = (const float*)d_in[5];
    const float* W2   = (const float*)d_in[6];
    const float* aS2  = (const float*)d_in[7];
    const float* aD2  = (const float*)d_in[8];
    const float* b2   = (const float*)d_in[9];
    const float* W3   = (const float*)d_in[10];
    const float* aS3  = (const float*)d_in[11];
    const float* aD3  = (const float*)d_in[12];
    const float* b3   = (const float*)d_in[13];
    const float* regw = (const float*)d_in[14];
    const float* regb = (const float*)d_in[15];
    const float* clsw = (const float*)d_in[16];
    const float* clsb = (const float*)d_in[17];
    float* out = (float*)d_out;

    const int* src = ei;
    const int* dst = ei + NE;

    // 1. front: zero cursors + W2 transpose + prep1
    k_front<<<NBLK + 65, 256>>>(W2, W1, aS1, aD1);
    // 2. histogram + layer-1 logits (merged, disjoint block ranges)
    k_histlog<<<3126, 256>>>(dst, x);
    // 3-5. hierarchical scan -> g_off, g_cur
    k_bsum<<<NBLK, 256>>>();
    k_bscan<<<1, 512>>>();
    k_local<<<NBLK, 256>>>();
    // 6. reorder
    k_reorder<<<(NE / 4 + 255) / 256, 256>>>(src, dst);
    // 7. layer 1 gather (x-space)
    k_gx<<<12500, 256>>>(x, W1, b1);
    // 8-9. layer 2: HMMA GEMM with fused logits, gather (+residual)
    k_gemm2<<<3125, 256>>>(aS2, aD2);
    k_gather4<<<12500, 256>>>(b2);
    // 10-11. layer 3 + output heads
    k_gemm3<<<3125, 128>>>(W3, aS3, aD3);
    k_gather1<<<12500, 256>>>(b3, regw, regb, clsw, clsb, out);
}